// round 13
// baseline (speedup 1.0000x reference)
#include <cuda_runtime.h>
#include <math.h>
#include <float.h>
#include <stdint.h>

// ---------------------------------------------------------------------------
// ConvKAN3D fused pipeline, R11 = R6 (best, 377us) with grid-shape changes ONLY:
//  - block3: CTILE=2 -> grid 512 (was 256; occupancy was grid-limited)
//  - block1: 2 channel-groups of 16 -> grid 1024 (was 512; grid-limited)
//  Inner loops byte-identical to R6.
// ---------------------------------------------------------------------------

using u64 = unsigned long long;

__device__ __forceinline__ u64 pk2(float lo, float hi) {
    u64 r; asm("mov.b64 %0,{%1,%2};" : "=l"(r) : "f"(lo), "f"(hi)); return r;
}
__device__ __forceinline__ void up2(u64 v, float& lo, float& hi) {
    asm("mov.b64 {%0,%1}, %2;" : "=f"(lo), "=f"(hi) : "l"(v));
}
__device__ __forceinline__ void ffma2(u64& d, u64 a, u64 b) {
    asm("fma.rn.f32x2 %0, %1, %2, %0;" : "+l"(d) : "l"(a), "l"(b));
}
__device__ __forceinline__ u64 midp(u64 A, u64 B) {
    float al, ah, bl, bh; up2(A, al, ah); up2(B, bl, bh); return pk2(ah, bl);
}
__device__ __forceinline__ void cpa16(uint32_t dst, const float* src) {
    asm volatile("cp.async.ca.shared.global [%0], [%1], 16;" :: "r"(dst), "l"(src));
}
__device__ __forceinline__ void cpa_commit() {
    asm volatile("cp.async.commit_group;");
}
template<int N>
__device__ __forceinline__ void cpa_wait() {
    asm volatile("cp.async.wait_group %0;" :: "n"(N));
}

// Padded scratch (zero-initialized device globals; halos never written).
__device__ __align__(16) float g_xp [2u * 66u * 66u * 66u];              // 2.3 MB
__device__ __align__(16) float g_s1p[2u * 32u * 36u * 36u * 36u];        // 11.9 MB
__device__ __align__(16) float g_s2p[2u * 64u * 20u * 20u * 20u];        // 4.1 MB
__device__ __align__(16) float g_s3 [2u * 128u * 512u];                  // 0.5 MB
__device__ float4 g_coef[224 * 11];
__device__ float  g_mean[2 * 128];

// --- piecewise cubic coefficients -------------------------------------------
__global__ void coef_kernel(const float* __restrict__ k1, const float* __restrict__ sw1,
                            const float* __restrict__ k2, const float* __restrict__ sw2,
                            const float* __restrict__ k3, const float* __restrict__ sw3)
{
    const int t = threadIdx.x;
    if (t >= 224) return;
    const float* kn; const float* sw;
    if (t < 32)       { kn = k1; sw = sw1 + t * 10; }
    else if (t < 96)  { kn = k2; sw = sw2 + (t - 32) * 10; }
    else              { kn = k3; sw = sw3 + (t - 96) * 10; }

    float4 a = make_float4(0.f, 0.f, 0.f, 0.f);
    g_coef[t * 11 + 0] = a;
    for (int e = 1; e <= 10; ++e) {
        const float tk = kn[e - 1];
        const float s  = sw[e - 1];
        a.x = fmaf(-s * tk * tk, tk, a.x);
        a.y = fmaf(3.f * s * tk, tk, a.y);
        a.z = fmaf(-3.f * s, tk, a.z);
        a.w += s;
        g_coef[t * 11 + e] = a;
    }
}

// --- copy x into padded buffer ----------------------------------------------
__global__ void pad_x_kernel(const float* __restrict__ x)
{
    const int idx = blockIdx.x * blockDim.x + threadIdx.x;   // 2*64^3
    if (idx >= 2 * 262144) return;
    const int ix = idx & 63, iy = (idx >> 6) & 63, iz = (idx >> 12) & 63;
    const int b  = idx >> 18;
    g_xp[(((size_t)b * 66 + iz + 1) * 66 + iy + 1) * 66 + ix + 1] = x[idx];
}

// --- pointwise epilogue helper ----------------------------------------------
__device__ __forceinline__ float pointwise(float y, const float4* coef,
                                           float w1, float w2, float scale, float beta)
{
    int e = __float2int_rd((y + 1.0f) * 4.5f) + 1;
    e = max(0, min(10, e));
    const float4 cf = coef[e];
    const float sp  = fmaf(fmaf(fmaf(cf.w, y, cf.z), y, cf.y), y, cf.x);
    const float sig = 1.0f / (1.0f + __expf(-y));
    return fmaf(w1 * sp + w2 * (y * sig), scale, beta);
}

// --- Block 1: CIN=1, 16 channels per thread (2 channel groups) ---------------
__global__ void __launch_bounds__(128)
block1_kernel(const float* __restrict__ cw,   // [32,1,27]
              const float* __restrict__ cb,
              const float* __restrict__ w1p, const float* __restrict__ w2p,
              const float* __restrict__ gp,  const float* __restrict__ bp,
              float* __restrict__ out)        // padded [2,32,36^3]
{
    constexpr int Din = 66, P = 32, SO = 36;

    __shared__ u64    s_w[32 * 27];            // packed {w,w}
    __shared__ float4 s_coef[32 * 11];
    __shared__ float  s_bias[32], s_w1[32], s_w2[32], s_scale[32], s_beta[32];

    for (int i = threadIdx.x; i < 32 * 27; i += 128) {
        const float w = cw[i];
        s_w[i] = pk2(w, w);
    }
    for (int i = threadIdx.x; i < 32 * 11; i += 128) s_coef[i] = g_coef[i];
    if (threadIdx.x < 32) {
        const int c = threadIdx.x;
        s_bias[c]  = cb[c];  s_w1[c] = w1p[c];  s_w2[c] = w2p[c];
        s_scale[c] = gp[c] * rsqrtf(1.0f + 1e-5f);  s_beta[c] = bp[c];
    }
    __syncthreads();

    const int vox = blockIdx.x * 128 + threadIdx.x;   // 0..32767
    const int c0  = blockIdx.y * 16;                  // channel group
    const int b   = blockIdx.z;
    const int px = vox % P, py = (vox / P) % P, pz = vox / (P * P);

    const u64* inb = (const u64*)(g_xp + (size_t)b * Din * Din * Din);
    const int ib2  = (((2 * pz) * Din + 2 * py) * Din + 2 * px) >> 1;

    u64 A[16], Bv[16], M[16];
    #pragma unroll
    for (int a = 0; a < 4; ++a)
        #pragma unroll
        for (int r = 0; r < 4; ++r) {
            const int o = ib2 + ((((a)*Din + r) * Din) >> 1);
            A[a * 4 + r]  = inb[o];
            Bv[a * 4 + r] = inb[o + 1];
        }
    #pragma unroll
    for (int i = 0; i < 16; ++i) M[i] = midp(A[i], Bv[i]);

    #pragma unroll 1
    for (int c = c0; c < c0 + 16; ++c) {
        const float bi = s_bias[c];
        u64 acc[4];
        #pragma unroll
        for (int j = 0; j < 4; ++j) acc[j] = pk2(bi, bi);

        const u64* wp = s_w + c * 27;
        #pragma unroll
        for (int tap = 0; tap < 27; ++tap) {
            const int kd = tap / 9, kh = (tap / 3) % 3, kw = tap % 3;
            const u64 ww = wp[tap];
            #pragma unroll
            for (int dz = 0; dz < 2; ++dz)
                #pragma unroll
                for (int dy = 0; dy < 2; ++dy) {
                    const int ri = (dz + kd) * 4 + dy + kh;
                    const u64 src = (kw == 0) ? A[ri] : (kw == 2) ? Bv[ri] : M[ri];
                    ffma2(acc[dz * 2 + dy], ww, src);
                }
        }

        float mv = -FLT_MAX;
        #pragma unroll
        for (int j = 0; j < 4; ++j) {
            float y0, y1; up2(acc[j], y0, y1);
            mv = fmaxf(mv, pointwise(y0, s_coef + c * 11, s_w1[c], s_w2[c], s_scale[c], s_beta[c]));
            mv = fmaxf(mv, pointwise(y1, s_coef + c * 11, s_w1[c], s_w2[c], s_scale[c], s_beta[c]));
        }
        out[((((size_t)b * 32 + c) * SO + pz + 1) * SO + py + 1) * SO + px + 1] = mv;
    }
}

// --- Blocks 2 & 3: cp.async double-buffered fused conv block (R6 loop) ------
// CTA = 8x4x4 pooled tile, 128 threads, CTILE output channels (smem weights).
template<int CIN, int P, int SIN, int SOUT, int COUT, int CTILE>
__global__ void __launch_bounds__(128)
conv_block(const float* __restrict__ in,     // padded [2,CIN,SIN^3]
           const float* __restrict__ cw,     // [COUT,CIN,27]
           const float* __restrict__ cb,
           const float* __restrict__ w1p, const float* __restrict__ w2p,
           const float* __restrict__ gp,  const float* __restrict__ bp,
           float* __restrict__ out, int coefBase)
{
    constexpr int TRS    = 20;                 // tile row stride (floats)
    constexpr int TILE_F = 10 * 10 * TRS;      // 2000 floats per buffer
    constexpr int NTX = P / 8, NTY = P / 4;

    const int cobase = blockIdx.y * CTILE;
    const int b      = blockIdx.z;
    const int tx =  blockIdx.x % NTX;
    const int ty = (blockIdx.x / NTX) % NTY;
    const int tz =  blockIdx.x / (NTX * NTY);
    const int x0 = 16 * tx, y0 = 8 * ty, z0 = 8 * tz;   // padded input origin

    __shared__ float  s_w[CIN * 27 * CTILE];   // [ci][tap][t]
    __shared__ __align__(16) float s_tile[2][TILE_F];
    __shared__ float4 s_coef[CTILE * 11];
    __shared__ float  s_bias[CTILE], s_w1[CTILE], s_w2[CTILE],
                      s_scale[CTILE], s_beta[CTILE];

    const int tid = threadIdx.x;

    for (int i = tid; i < CIN * 27 * CTILE; i += 128) {
        const int t   = i % CTILE;
        const int tap = (i / CTILE) % 27;
        const int ci  = i / (CTILE * 27);
        s_w[i] = cw[((size_t)(cobase + t) * CIN + ci) * 27 + tap];
    }
    for (int i = tid; i < CTILE * 11; i += 128)
        s_coef[i] = g_coef[(coefBase + cobase) * 11 + i];
    if (tid < CTILE) {
        const int c = cobase + tid;
        s_bias[tid]  = cb[c];
        s_w1[tid]    = w1p[c];
        s_w2[tid]    = w2p[c];
        s_scale[tid] = gp[c] * rsqrtf(1.0f + 1e-5f);
        s_beta[tid]  = bp[c];
    }

    // Precompute loop-invariant cp.async offsets (4 fragments per thread).
    const float* chan0 = in + (size_t)b * CIN * SIN * SIN * SIN;
    int      soff[4];
    uint32_t doff[4];
    bool     sval[4];
    #pragma unroll
    for (int k = 0; k < 4; ++k) {
        const int f = tid + k * 128;
        sval[k] = (f < 500);
        const int fc  = sval[k] ? f : 0;
        const int row = fc / 5, xf = fc % 5;
        const int zr  = row / 10, yr = row % 10;
        soff[k] = ((z0 + zr) * SIN + (y0 + yr)) * SIN + x0 + xf * 4;
        doff[k] = (uint32_t)__cvta_generic_to_shared(
                      &s_tile[0][(zr * 10 + yr) * TRS + xf * 4]);
    }
    constexpr int CH_STRIDE = SIN * SIN * SIN;
    constexpr uint32_t BUF_BYTES = TILE_F * 4;

    // Prologue: stage ci=0 into buffer 0.
    #pragma unroll
    for (int k = 0; k < 4; ++k)
        if (sval[k]) cpa16(doff[k], chan0 + soff[k]);
    cpa_commit();

    const int lpx = tid & 7, lpy = (tid >> 3) & 3, lpz = tid >> 5;

    u64 acc[CTILE][4];
    #pragma unroll
    for (int t = 0; t < CTILE; ++t) {
        acc[t][0] = 0; acc[t][1] = 0; acc[t][2] = 0; acc[t][3] = 0;
    }

    #pragma unroll 1
    for (int ci = 0; ci < CIN; ++ci) {
        if (ci + 1 < CIN) {
            const float* src = chan0 + (size_t)(ci + 1) * CH_STRIDE;
            const uint32_t dadd = ((ci + 1) & 1) ? BUF_BYTES : 0u;
            #pragma unroll
            for (int k = 0; k < 4; ++k)
                if (sval[k]) cpa16(doff[k] + dadd, src + soff[k]);
            cpa_commit();
            cpa_wait<1>();
        } else {
            cpa_wait<0>();
        }
        __syncthreads();   // staged data visible to all threads; params staged

        if (ci == 0) {     // init accumulators with bias (params ready after barrier)
            #pragma unroll
            for (int t = 0; t < CTILE; ++t) {
                const u64 bb = pk2(s_bias[t], s_bias[t]);
                #pragma unroll
                for (int j = 0; j < 4; ++j) acc[t][j] = bb;
            }
        }

        const float* tp = s_tile[ci & 1];

        u64 A[16], Bv[16], M[16];
        #pragma unroll
        for (int a = 0; a < 4; ++a)
            #pragma unroll
            for (int r = 0; r < 4; ++r) {
                const float* rowp = tp + ((2 * lpz + a) * 10 + 2 * lpy + r) * TRS + 2 * lpx;
                A[a * 4 + r]  = *(const u64*)rowp;
                Bv[a * 4 + r] = *(const u64*)(rowp + 2);
            }
        #pragma unroll
        for (int i = 0; i < 16; ++i) M[i] = midp(A[i], Bv[i]);

        const float* wp = s_w + ci * 27 * CTILE;
        #pragma unroll
        for (int tap = 0; tap < 27; ++tap) {
            const int kd = tap / 9, kh = (tap / 3) % 3, kw = tap % 3;
            float wv[CTILE];
            if (CTILE == 4) {
                const float4 w4 = *(const float4*)(wp + tap * CTILE);
                wv[0] = w4.x; wv[1] = w4.y; wv[2] = w4.z; wv[3] = w4.w;
            } else {
                const float2 w2 = *(const float2*)(wp + tap * CTILE);
                wv[0] = w2.x; wv[1] = w2.y;
            }
            #pragma unroll
            for (int t = 0; t < CTILE; ++t) {
                const u64 ww = pk2(wv[t], wv[t]);
                #pragma unroll
                for (int dz = 0; dz < 2; ++dz)
                    #pragma unroll
                    for (int dy = 0; dy < 2; ++dy) {
                        const int ri = (dz + kd) * 4 + dy + kh;
                        const u64 src = (kw == 0) ? A[ri] : (kw == 2) ? Bv[ri] : M[ri];
                        ffma2(acc[t][dz * 2 + dy], ww, src);
                    }
            }
        }
        __syncthreads();   // done reading this buffer before it is re-staged
    }

    // pooled output coordinates
    const int gpx = 8 * tx + lpx, gpy = 4 * ty + lpy, gpz = 4 * tz + lpz;

    #pragma unroll
    for (int t = 0; t < CTILE; ++t) {
        float mv = -FLT_MAX;
        #pragma unroll
        for (int j = 0; j < 4; ++j) {
            float y0v, y1v; up2(acc[t][j], y0v, y1v);
            mv = fmaxf(mv, pointwise(y0v, s_coef + t * 11, s_w1[t], s_w2[t], s_scale[t], s_beta[t]));
            mv = fmaxf(mv, pointwise(y1v, s_coef + t * 11, s_w1[t], s_w2[t], s_scale[t], s_beta[t]));
        }
        const int c = cobase + t;
        if (SOUT > 0)
            out[((((size_t)b * COUT + c) * SOUT + gpz + 1) * SOUT + gpy + 1) * SOUT + gpx + 1] = mv;
        else  // compact [2, COUT, P^3]
            out[((size_t)b * COUT + c) * (P * P * P) + (gpz * P + gpy) * P + gpx] = mv;
    }
}

// --- Head --------------------------------------------------------------------
__global__ void __launch_bounds__(64)
mean_kernel(const float* __restrict__ s3)
{
    const int bc = blockIdx.x;
    const int t  = threadIdx.x;
    const float* p = s3 + (size_t)bc * 512;

    float s = 0.0f;
    #pragma unroll
    for (int i = 0; i < 8; ++i) s += p[t + i * 64];
    #pragma unroll
    for (int off = 16; off > 0; off >>= 1)
        s += __shfl_down_sync(0xffffffffu, s, off);
    __shared__ float part[2];
    if ((t & 31) == 0) part[t >> 5] = s;
    __syncthreads();
    if (t == 0) g_mean[bc] = (part[0] + part[1]) * (1.0f / 512.0f);
}

__global__ void __launch_bounds__(256)
fc_kernel(const float* __restrict__ fc1w, const float* __restrict__ fc1b,
          const float* __restrict__ fc2w, const float* __restrict__ fc2b,
          float* __restrict__ out)
{
    const int t = threadIdx.x;
    __shared__ float m[2][128];
    __shared__ float h[2][256];

    if (t < 128) { m[0][t] = g_mean[t]; m[1][t] = g_mean[128 + t]; }
    __syncthreads();

    #pragma unroll
    for (int b = 0; b < 2; ++b) {
        float s = fc1b[t];
        const float* w = fc1w + t * 128;
        #pragma unroll 8
        for (int k = 0; k < 128; ++k) s = fmaf(m[b][k], w[k], s);
        h[b][t] = fmaxf(s, 0.0f);
    }
    __syncthreads();

    if (t < 4) {
        const int b = t >> 1, o = t & 1;
        float s = fc2b[o];
        const float* w = fc2w + o * 256;
        #pragma unroll 8
        for (int k = 0; k < 256; ++k) s = fmaf(h[b][k], w[k], s);
        out[b * 2 + o] = s;
    }
}

extern "C" void kernel_launch(void* const* d_in, const int* in_sizes, int n_in,
                              void* d_out, int out_size)
{
    (void)in_sizes; (void)n_in; (void)out_size;

    const float* x     = (const float*)d_in[0];
    const float* c1_w  = (const float*)d_in[1];
    const float* c1_b  = (const float*)d_in[2];
    const float* c1_k  = (const float*)d_in[3];
    const float* c1_sw = (const float*)d_in[4];
    const float* c1_w1 = (const float*)d_in[5];
    const float* c1_w2 = (const float*)d_in[6];
    const float* bn1_g = (const float*)d_in[7];
    const float* bn1_b = (const float*)d_in[8];
    const float* c2_w  = (const float*)d_in[9];
    const float* c2_b  = (const float*)d_in[10];
    const float* c2_k  = (const float*)d_in[11];
    const float* c2_sw = (const float*)d_in[12];
    const float* c2_w1 = (const float*)d_in[13];
    const float* c2_w2 = (const float*)d_in[14];
    const float* bn2_g = (const float*)d_in[15];
    const float* bn2_b = (const float*)d_in[16];
    const float* c3_w  = (const float*)d_in[17];
    const float* c3_b  = (const float*)d_in[18];
    const float* c3_k  = (const float*)d_in[19];
    const float* c3_sw = (const float*)d_in[20];
    const float* c3_w1 = (const float*)d_in[21];
    const float* c3_w2 = (const float*)d_in[22];
    const float* bn3_g = (const float*)d_in[23];
    const float* bn3_b = (const float*)d_in[24];
    const float* fc1_w = (const float*)d_in[25];
    const float* fc1_b = (const float*)d_in[26];
    const float* fc2_w = (const float*)d_in[27];
    const float* fc2_b = (const float*)d_in[28];
    float* out = (float*)d_out;

    float *s1p, *s2p, *s3;
    cudaGetSymbolAddress((void**)&s1p, g_s1p);
    cudaGetSymbolAddress((void**)&s2p, g_s2p);
    cudaGetSymbolAddress((void**)&s3,  g_s3);

    coef_kernel<<<1, 224>>>(c1_k, c1_sw, c2_k, c2_sw, c3_k, c3_sw);
    pad_x_kernel<<<(2 * 262144 + 255) / 256, 256>>>(x);

    // Block 1: CIN=1, D=64, 2 channel groups -> s1p (stride-36 padded)
    block1_kernel<<<dim3(32768 / 128, 2, 2), 128>>>(
        c1_w, c1_b, c1_w1, c1_w2, bn1_g, bn1_b, s1p);

    // Block 2: CIN=32, P=16, SIN=36, CTILE=4 -> s2p (stride-20 padded)
    conv_block<32, 16, 36, 20, 64, 4><<<dim3(32, 16, 2), 128>>>(
        s1p, c2_w, c2_b, c2_w1, c2_w2, bn2_g, bn2_b, s2p, 32);

    // Block 3: CIN=64, P=8, SIN=20, CTILE=2 -> s3 (compact 8^3), grid 512
    conv_block<64, 8, 20, 0, 128, 2><<<dim3(4, 64, 2), 128>>>(
        s2p, c3_w, c3_b, c3_w1, c3_w2, bn3_g, bn3_b, s3, 96);

    mean_kernel<<<256, 64>>>(s3);
    fc_kernel<<<1, 256>>>(fc1_w, fc1_b, fc2_w, fc2_b, out);
}

// round 15
// speedup vs baseline: 1.1520x; 1.1520x over previous
#include <cuda_runtime.h>
#include <math.h>
#include <float.h>
#include <stdint.h>

using u64 = unsigned long long;

__device__ __forceinline__ u64 pk2(float lo, float hi) {
    u64 r; asm("mov.b64 %0,{%1,%2};" : "=l"(r) : "f"(lo), "f"(hi)); return r;
}
__device__ __forceinline__ void up2(u64 v, float& lo, float& hi) {
    asm("mov.b64 {%0,%1}, %2;" : "=f"(lo), "=f"(hi) : "l"(v));
}
__device__ __forceinline__ void ffma2(u64& d, u64 a, u64 b) {
    asm("fma.rn.f32x2 %0, %1, %2, %0;" : "+l"(d) : "l"(a), "l"(b));
}
__device__ __forceinline__ u64 midp(u64 A, u64 B) {
    float al, ah, bl, bh; up2(A, al, ah); up2(B, bl, bh); return pk2(ah, bl);
}
__device__ __forceinline__ void cpa16(uint32_t dst, const float* src) {
    asm volatile("cp.async.ca.shared.global [%0], [%1], 16;" :: "r"(dst), "l"(src));
}
__device__ __forceinline__ void cpa_commit() { asm volatile("cp.async.commit_group;"); }
template<int N>
__device__ __forceinline__ void cpa_wait() { asm volatile("cp.async.wait_group %0;" :: "n"(N)); }
__device__ __forceinline__ uint32_t smem_u32(const void* p) {
    return (uint32_t)__cvta_generic_to_shared(p);
}
__device__ __forceinline__ float tf32r(float f) {
    uint32_t t; asm("cvt.rna.tf32.f32 %0, %1;" : "=r"(t) : "f"(f));
    return __uint_as_float(t);
}
// mma.sync m16n8k8 tf32 (sm_80+, target-portable)
__device__ __forceinline__ void mma16n8k8(float* d, const uint32_t* a, uint32_t b0, uint32_t b1) {
    asm("mma.sync.aligned.m16n8k8.row.col.f32.tf32.tf32.f32 "
        "{%0,%1,%2,%3},{%4,%5,%6,%7},{%8,%9},{%0,%1,%2,%3};"
        : "+f"(d[0]), "+f"(d[1]), "+f"(d[2]), "+f"(d[3])
        : "r"(a[0]), "r"(a[1]), "r"(a[2]), "r"(a[3]), "r"(b0), "r"(b1));
}

// Scratch (zero-initialized device globals; halos never written).
__device__ __align__(16) float g_xp [2u * 66u * 66u * 66u];
__device__ __align__(16) float g_s1n[2u * 34u * 34u * 34u * 32u];   // NHWC tf32
__device__ __align__(16) float g_s2p[2u * 64u * 20u * 20u * 20u];
__device__ __align__(16) float g_s3 [2u * 128u * 512u];
__device__ __align__(16) float g_wB [27 * 4 * 8 * 32 * 2];          // mma-frag order
__device__ float4 g_coef[224 * 11];
__device__ float  g_mean[2 * 128];

__global__ void coef_kernel(const float* __restrict__ k1, const float* __restrict__ sw1,
                            const float* __restrict__ k2, const float* __restrict__ sw2,
                            const float* __restrict__ k3, const float* __restrict__ sw3)
{
    const int t = threadIdx.x;
    if (t >= 224) return;
    const float* kn; const float* sw;
    if (t < 32)       { kn = k1; sw = sw1 + t * 10; }
    else if (t < 96)  { kn = k2; sw = sw2 + (t - 32) * 10; }
    else              { kn = k3; sw = sw3 + (t - 96) * 10; }
    float4 a = make_float4(0.f, 0.f, 0.f, 0.f);
    g_coef[t * 11 + 0] = a;
    for (int e = 1; e <= 10; ++e) {
        const float tk = kn[e - 1], s = sw[e - 1];
        a.x = fmaf(-s * tk * tk, tk, a.x);
        a.y = fmaf(3.f * s * tk, tk, a.y);
        a.z = fmaf(-3.f * s, tk, a.z);
        a.w += s;
        g_coef[t * 11 + e] = a;
    }
}

// Rearrange conv2 weights into mma B-fragment order:
// [tap][kc][nt][lane][half]; b = W[co=8nt+gid][ci=8kc+tig+4*half], tf32-rounded.
__global__ void rearrange_wB(const float* __restrict__ cw2)   // [64,32,27]
{
    const int i = blockIdx.x * 256 + threadIdx.x;
    if (i >= 27 * 4 * 8 * 32 * 2) return;
    const int half = i & 1;
    const int lane = (i >> 1) & 31;
    const int nt   = (i >> 6) & 7;
    const int kc   = (i >> 9) & 3;
    const int tap  = i >> 11;
    const int gid = lane >> 2, tig = lane & 3;
    const int co = 8 * nt + gid;
    const int ci = 8 * kc + tig + 4 * half;
    g_wB[i] = tf32r(cw2[(co * 32 + ci) * 27 + tap]);
}

__global__ void pad_x_kernel(const float* __restrict__ x)
{
    const int idx = blockIdx.x * blockDim.x + threadIdx.x;
    if (idx >= 2 * 262144) return;
    const int ix = idx & 63, iy = (idx >> 6) & 63, iz = (idx >> 12) & 63;
    const int b  = idx >> 18;
    g_xp[(((size_t)b * 66 + iz + 1) * 66 + iy + 1) * 66 + ix + 1] = x[idx];
}

__device__ __forceinline__ float pointwise(float y, const float4* coef,
                                           float w1, float w2, float scale, float beta)
{
    int e = __float2int_rd((y + 1.0f) * 4.5f) + 1;
    e = max(0, min(10, e));
    const float4 cf = coef[e];
    const float sp  = fmaf(fmaf(fmaf(cf.w, y, cf.z), y, cf.y), y, cf.x);
    const float sig = 1.0f / (1.0f + __expf(-y));
    return fmaf(w1 * sp + w2 * (y * sig), scale, beta);
}

// --- Block 1: scalar, outputs NHWC tf32-rounded s1n --------------------------
__global__ void __launch_bounds__(128)
block1_kernel(const float* __restrict__ cw, const float* __restrict__ cb,
              const float* __restrict__ w1p, const float* __restrict__ w2p,
              const float* __restrict__ gp,  const float* __restrict__ bp,
              float* __restrict__ out)        // NHWC [2,34,34,34,32]
{
    constexpr int Din = 66, P = 32;
    __shared__ u64    s_w[32 * 27];
    __shared__ float4 s_coef[32 * 11];
    __shared__ float  s_bias[32], s_w1[32], s_w2[32], s_scale[32], s_beta[32];

    for (int i = threadIdx.x; i < 32 * 27; i += 128) { const float w = cw[i]; s_w[i] = pk2(w, w); }
    for (int i = threadIdx.x; i < 32 * 11; i += 128) s_coef[i] = g_coef[i];
    if (threadIdx.x < 32) {
        const int c = threadIdx.x;
        s_bias[c] = cb[c]; s_w1[c] = w1p[c]; s_w2[c] = w2p[c];
        s_scale[c] = gp[c] * rsqrtf(1.0f + 1e-5f); s_beta[c] = bp[c];
    }
    __syncthreads();

    const int vox = blockIdx.x * 128 + threadIdx.x;
    const int c0  = blockIdx.y * 16;
    const int b   = blockIdx.z;
    const int px = vox % P, py = (vox / P) % P, pz = vox / (P * P);

    const u64* inb = (const u64*)(g_xp + (size_t)b * Din * Din * Din);
    const int ib2  = (((2 * pz) * Din + 2 * py) * Din + 2 * px) >> 1;

    u64 A[16], Bv[16], M[16];
    #pragma unroll
    for (int a = 0; a < 4; ++a)
        #pragma unroll
        for (int r = 0; r < 4; ++r) {
            const int o = ib2 + (((a * Din + r) * Din) >> 1);
            A[a * 4 + r] = inb[o]; Bv[a * 4 + r] = inb[o + 1];
        }
    #pragma unroll
    for (int i = 0; i < 16; ++i) M[i] = midp(A[i], Bv[i]);

    float* orow = out + ((((size_t)b * 34 + pz + 1) * 34 + py + 1) * 34 + px + 1) * 32;

    #pragma unroll 1
    for (int c = c0; c < c0 + 16; ++c) {
        const float bi = s_bias[c];
        u64 acc[4];
        #pragma unroll
        for (int j = 0; j < 4; ++j) acc[j] = pk2(bi, bi);
        const u64* wp = s_w + c * 27;
        #pragma unroll
        for (int tap = 0; tap < 27; ++tap) {
            const int kd = tap / 9, kh = (tap / 3) % 3, kw = tap % 3;
            const u64 ww = wp[tap];
            #pragma unroll
            for (int dz = 0; dz < 2; ++dz)
                #pragma unroll
                for (int dy = 0; dy < 2; ++dy) {
                    const int ri = (dz + kd) * 4 + dy + kh;
                    const u64 src = (kw == 0) ? A[ri] : (kw == 2) ? Bv[ri] : M[ri];
                    ffma2(acc[dz * 2 + dy], ww, src);
                }
        }
        float mv = -FLT_MAX;
        #pragma unroll
        for (int j = 0; j < 4; ++j) {
            float y0, y1; up2(acc[j], y0, y1);
            mv = fmaxf(mv, pointwise(y0, s_coef + c * 11, s_w1[c], s_w2[c], s_scale[c], s_beta[c]));
            mv = fmaxf(mv, pointwise(y1, s_coef + c * 11, s_w1[c], s_w2[c], s_scale[c], s_beta[c]));
        }
        orow[c] = tf32r(mv);
    }
}

// --- Block 2: mma.sync tf32 implicit GEMM ------------------------------------
// CTA: M=128 pre-pool voxels (32x,2y,2z) x N=64 cout, K=32 cin, 27 taps.
// 4 warps: warp w owns rows [32w,32w+32). acc[2 mt][8 nt][4].
__global__ void __launch_bounds__(128)
gemm2_kernel(const float* __restrict__ cb,
             const float* __restrict__ w1p, const float* __restrict__ w2p,
             const float* __restrict__ gp,  const float* __restrict__ bp,
             float* __restrict__ out)        // s2p padded [2,64,20,20,20]
{
    constexpr int ATRS = 36;                        // A row stride (floats)
    constexpr int ABUF = 128 * ATRS;                // 4608 floats = 18432 B
    constexpr int BBUF = 2048;                      // floats = 8192 B
    extern __shared__ float dyn[];
    float* As = dyn;                                // 2 x ABUF
    float* Bs = dyn + 2 * ABUF;                     // 2 x BBUF

    __shared__ float4 s_coef[64 * 11];
    __shared__ float  s_bias[64], s_w1[64], s_w2[64], s_scale[64], s_beta[64];

    const int tid = threadIdx.x;
    const int wid = tid >> 5, lane = tid & 31;
    const int gid = lane >> 2, tig = lane & 3;
    const int ty = blockIdx.x, tz = blockIdx.y, b = blockIdx.z;

    for (int i = tid; i < 64 * 11; i += 128) s_coef[i] = g_coef[(32 + i / 11) * 11 + i % 11];
    if (tid < 64) {
        s_bias[tid] = cb[tid]; s_w1[tid] = w1p[tid]; s_w2[tid] = w2p[tid];
        s_scale[tid] = gp[tid] * rsqrtf(1.0f + 1e-5f); s_beta[tid] = bp[tid];
    }

    const float* in_b = g_s1n + (size_t)b * 34 * 34 * 34 * 32;
    const int x = tid & 31, dy = (tid >> 5) & 1, dz = tid >> 6;
    const uint32_t Abase = smem_u32(As), Bbase = smem_u32(Bs);

    auto stage = [&](int t, int buf) {
        const int kz = t / 9, ky = (t / 3) % 3, kx = t % 3;
        const float* src = in_b +
            ((((size_t)(2 * tz + dz + kz)) * 34 + (2 * ty + dy + ky)) * 34 + (x + kx)) * 32;
        const uint32_t ad = Abase + (uint32_t)buf * (ABUF * 4) + (uint32_t)tid * (ATRS * 4);
        #pragma unroll
        for (int ch = 0; ch < 8; ++ch) cpa16(ad + ch * 16, src + ch * 4);
        const float* wsrc = g_wB + (size_t)t * BBUF;
        const uint32_t bd = Bbase + (uint32_t)buf * (BBUF * 4);
        #pragma unroll
        for (int j = 0; j < 4; ++j) {
            const int idx = tid + j * 128;
            cpa16(bd + (uint32_t)idx * 16, wsrc + idx * 4);
        }
    };

    float acc[2][8][4];
    #pragma unroll
    for (int mt = 0; mt < 2; ++mt)
        #pragma unroll
        for (int nt = 0; nt < 8; ++nt)
            #pragma unroll
            for (int j = 0; j < 4; ++j) acc[mt][nt][j] = 0.0f;

    stage(0, 0);
    cpa_commit();

    const int Rbase = wid * 32;

    #pragma unroll 1
    for (int t = 0; t < 27; ++t) {
        if (t < 26) {
            stage(t + 1, (t + 1) & 1);
            cpa_commit();
            cpa_wait<1>();
        } else {
            cpa_wait<0>();
        }
        __syncthreads();

        const float* Ab = As + (t & 1) * ABUF;
        const float* Bb = Bs + (t & 1) * BBUF;

        #pragma unroll
        for (int kc = 0; kc < 4; ++kc) {
            uint32_t a[2][4];
            #pragma unroll
            for (int mt = 0; mt < 2; ++mt)
                #pragma unroll
                for (int s = 0; s < 4; ++s)
                    a[mt][s] = __float_as_uint(
                        Ab[(Rbase + 16 * mt + gid + 8 * (s & 1)) * ATRS
                           + 8 * kc + tig + 4 * (s >> 1)]);
            #pragma unroll
            for (int nt = 0; nt < 8; ++nt) {
                const float2 bb = *(const float2*)(Bb + ((kc * 8 + nt) * 32 + lane) * 2);
                const uint32_t b0 = __float_as_uint(bb.x), b1 = __float_as_uint(bb.y);
                mma16n8k8(acc[0][nt], a[0], b0, b1);
                mma16n8k8(acc[1][nt], a[1], b0, b1);
            }
        }
        __syncthreads();
    }

    // Epilogue: pointwise into pw[row*65 + c] (reuses A region), then pooled max.
    float* pw = As;
    #pragma unroll
    for (int mt = 0; mt < 2; ++mt)
        #pragma unroll
        for (int nt = 0; nt < 8; ++nt)
            #pragma unroll
            for (int cj = 0; cj < 4; ++cj) {
                const int row = Rbase + 16 * mt + gid + 8 * (cj >> 1);
                const int c   = 8 * nt + 2 * tig + (cj & 1);
                const float y = acc[mt][nt][cj] + s_bias[c];
                pw[row * 65 + c] =
                    pointwise(y, s_coef + c * 11, s_w1[c], s_w2[c], s_scale[c], s_beta[c]);
            }
    __syncthreads();

    #pragma unroll
    for (int j = 0; j < 8; ++j) {
        const int idx = tid + j * 128;          // 1024 outputs
        const int c = idx & 63, xh = idx >> 6;  // xh in [0,16)
        float mv = -FLT_MAX;
        #pragma unroll
        for (int q = 0; q < 8; ++q) {
            const int m = 2 * xh + (q & 1) + 32 * ((q >> 1) & 1) + 64 * (q >> 2);
            mv = fmaxf(mv, pw[m * 65 + c]);
        }
        out[((((size_t)b * 64 + c) * 20 + tz + 1) * 20 + ty + 1) * 20 + xh + 1] = mv;
    }
}

// --- Block 3: scalar cp.async conv block (proven R6 core, CTILE=2) -----------
template<int CIN, int P, int SIN, int COUT, int CTILE>
__global__ void __launch_bounds__(128)
conv_block(const float* __restrict__ in, const float* __restrict__ cw,
           const float* __restrict__ cb,
           const float* __restrict__ w1p, const float* __restrict__ w2p,
           const float* __restrict__ gp,  const float* __restrict__ bp,
           float* __restrict__ out, int coefBase)
{
    constexpr int TRS = 20, TILE_F = 10 * 10 * TRS;
    constexpr int NTX = P / 8, NTY = P / 4;
    const int cobase = blockIdx.y * CTILE;
    const int b = blockIdx.z;
    const int tx = blockIdx.x % NTX, ty = (blockIdx.x / NTX) % NTY, tz = blockIdx.x / (NTX * NTY);
    const int x0 = 16 * tx, y0 = 8 * ty, z0 = 8 * tz;

    __shared__ float s_w[CIN * 27 * CTILE];
    __shared__ __align__(16) float s_tile[2][TILE_F];
    __shared__ float4 s_coef[CTILE * 11];
    __shared__ float s_bias[CTILE], s_w1[CTILE], s_w2[CTILE], s_scale[CTILE], s_beta[CTILE];

    const int tid = threadIdx.x;
    for (int i = tid; i < CIN * 27 * CTILE; i += 128) {
        const int t = i % CTILE, tap = (i / CTILE) % 27, ci = i / (CTILE * 27);
        s_w[i] = cw[((size_t)(cobase + t) * CIN + ci) * 27 + tap];
    }
    for (int i = tid; i < CTILE * 11; i += 128) s_coef[i] = g_coef[(coefBase + cobase) * 11 + i];
    if (tid < CTILE) {
        const int c = cobase + tid;
        s_bias[tid] = cb[c]; s_w1[tid] = w1p[c]; s_w2[tid] = w2p[c];
        s_scale[tid] = gp[c] * rsqrtf(1.0f + 1e-5f); s_beta[tid] = bp[c];
    }

    const float* chan0 = in + (size_t)b * CIN * SIN * SIN * SIN;
    int soff[4]; uint32_t doff[4]; bool sval[4];
    #pragma unroll
    for (int k = 0; k < 4; ++k) {
        const int f = tid + k * 128;
        sval[k] = (f < 500);
        const int fc = sval[k] ? f : 0;
        const int row = fc / 5, xf = fc % 5, zr = row / 10, yr = row % 10;
        soff[k] = ((z0 + zr) * SIN + (y0 + yr)) * SIN + x0 + xf * 4;
        doff[k] = smem_u32(&s_tile[0][(zr * 10 + yr) * TRS + xf * 4]);
    }
    constexpr int CH_STRIDE = SIN * SIN * SIN;
    constexpr uint32_t BUF_BYTES = TILE_F * 4;

    #pragma unroll
    for (int k = 0; k < 4; ++k) if (sval[k]) cpa16(doff[k], chan0 + soff[k]);
    cpa_commit();

    const int lpx = tid & 7, lpy = (tid >> 3) & 3, lpz = tid >> 5;
    u64 acc[CTILE][4];
    #pragma unroll
    for (int t = 0; t < CTILE; ++t) { acc[t][0]=0; acc[t][1]=0; acc[t][2]=0; acc[t][3]=0; }

    #pragma unroll 1
    for (int ci = 0; ci < CIN; ++ci) {
        if (ci + 1 < CIN) {
            const float* src = chan0 + (size_t)(ci + 1) * CH_STRIDE;
            const uint32_t dadd = ((ci + 1) & 1) ? BUF_BYTES : 0u;
            #pragma unroll
            for (int k = 0; k < 4; ++k) if (sval[k]) cpa16(doff[k] + dadd, src + soff[k]);
            cpa_commit();
            cpa_wait<1>();
        } else cpa_wait<0>();
        __syncthreads();
        if (ci == 0) {
            #pragma unroll
            for (int t = 0; t < CTILE; ++t) {
                const u64 bb = pk2(s_bias[t], s_bias[t]);
                #pragma unroll
                for (int j = 0; j < 4; ++j) acc[t][j] = bb;
            }
        }
        const float* tp = s_tile[ci & 1];
        u64 A[16], Bv[16], M[16];
        #pragma unroll
        for (int a = 0; a < 4; ++a)
            #pragma unroll
            for (int r = 0; r < 4; ++r) {
                const float* rowp = tp + ((2 * lpz + a) * 10 + 2 * lpy + r) * TRS + 2 * lpx;
                A[a * 4 + r] = *(const u64*)rowp;
                Bv[a * 4 + r] = *(const u64*)(rowp + 2);
            }
        #pragma unroll
        for (int i = 0; i < 16; ++i) M[i] = midp(A[i], Bv[i]);
        const float* wp = s_w + ci * 27 * CTILE;
        #pragma unroll
        for (int tap = 0; tap < 27; ++tap) {
            const int kd = tap / 9, kh = (tap / 3) % 3, kw = tap % 3;
            const float2 w2 = *(const float2*)(wp + tap * CTILE);
            const float wv[2] = { w2.x, w2.y };
            #pragma unroll
            for (int t = 0; t < CTILE; ++t) {
                const u64 ww = pk2(wv[t], wv[t]);
                #pragma unroll
                for (int dzz = 0; dzz < 2; ++dzz)
                    #pragma unroll
                    for (int dyy = 0; dyy < 2; ++dyy) {
                        const int ri = (dzz + kd) * 4 + dyy + kh;
                        const u64 src = (kw == 0) ? A[ri] : (kw == 2) ? Bv[ri] : M[ri];
                        ffma2(acc[t][dzz * 2 + dyy], ww, src);
                    }
            }
        }
        __syncthreads();
    }

    const int gpx = 8 * tx + lpx, gpy = 4 * ty + lpy, gpz = 4 * tz + lpz;
    #pragma unroll
    for (int t = 0; t < CTILE; ++t) {
        float mv = -FLT_MAX;
        #pragma unroll
        for (int j = 0; j < 4; ++j) {
            float y0v, y1v; up2(acc[t][j], y0v, y1v);
            mv = fmaxf(mv, pointwise(y0v, s_coef + t * 11, s_w1[t], s_w2[t], s_scale[t], s_beta[t]));
            mv = fmaxf(mv, pointwise(y1v, s_coef + t * 11, s_w1[t], s_w2[t], s_scale[t], s_beta[t]));
        }
        const int c = cobase + t;
        out[((size_t)b * COUT + c) * (P * P * P) + (gpz * P + gpy) * P + gpx] = mv;
    }
}

__global__ void __launch_bounds__(64)
mean_kernel(const float* __restrict__ s3)
{
    const int bc = blockIdx.x, t = threadIdx.x;
    const float* p = s3 + (size_t)bc * 512;
    float s = 0.0f;
    #pragma unroll
    for (int i = 0; i < 8; ++i) s += p[t + i * 64];
    #pragma unroll
    for (int off = 16; off > 0; off >>= 1) s += __shfl_down_sync(0xffffffffu, s, off);
    __shared__ float part[2];
    if ((t & 31) == 0) part[t >> 5] = s;
    __syncthreads();
    if (t == 0) g_mean[bc] = (part[0] + part[1]) * (1.0f / 512.0f);
}

__global__ void __launch_bounds__(256)
fc_kernel(const float* __restrict__ fc1w, const float* __restrict__ fc1b,
          const float* __restrict__ fc2w, const float* __restrict__ fc2b,
          float* __restrict__ out)
{
    const int t = threadIdx.x;
    __shared__ float m[2][128];
    __shared__ float h[2][256];
    if (t < 128) { m[0][t] = g_mean[t]; m[1][t] = g_mean[128 + t]; }
    __syncthreads();
    #pragma unroll
    for (int b = 0; b < 2; ++b) {
        float s = fc1b[t];
        const float* w = fc1w + t * 128;
        #pragma unroll 8
        for (int k = 0; k < 128; ++k) s = fmaf(m[b][k], w[k], s);
        h[b][t] = fmaxf(s, 0.0f);
    }
    __syncthreads();
    if (t < 4) {
        const int b = t >> 1, o = t & 1;
        float s = fc2b[o];
        const float* w = fc2w + o * 256;
        #pragma unroll 8
        for (int k = 0; k < 256; ++k) s = fmaf(h[b][k], w[k], s);
        out[b * 2 + o] = s;
    }
}

extern "C" void kernel_launch(void* const* d_in, const int* in_sizes, int n_in,
                              void* d_out, int out_size)
{
    (void)in_sizes; (void)n_in; (void)out_size;
    const float* x     = (const float*)d_in[0];
    const float* c1_w  = (const float*)d_in[1];
    const float* c1_b  = (const float*)d_in[2];
    const float* c1_k  = (const float*)d_in[3];
    const float* c1_sw = (const float*)d_in[4];
    const float* c1_w1 = (const float*)d_in[5];
    const float* c1_w2 = (const float*)d_in[6];
    const float* bn1_g = (const float*)d_in[7];
    const float* bn1_b = (const float*)d_in[8];
    const float* c2_w  = (const float*)d_in[9];
    const float* c2_b  = (const float*)d_in[10];
    const float* c2_k  = (const float*)d_in[11];
    const float* c2_sw = (const float*)d_in[12];
    const float* c2_w1 = (const float*)d_in[13];
    const float* c2_w2 = (const float*)d_in[14];
    const float* bn2_g = (const float*)d_in[15];
    const float* bn2_b = (const float*)d_in[16];
    const float* c3_w  = (const float*)d_in[17];
    const float* c3_b  = (const float*)d_in[18];
    const float* c3_k  = (const float*)d_in[19];
    const float* c3_sw = (const float*)d_in[20];
    const float* c3_w1 = (const float*)d_in[21];
    const float* c3_w2 = (const float*)d_in[22];
    const float* bn3_g = (const float*)d_in[23];
    const float* bn3_b = (const float*)d_in[24];
    const float* fc1_w = (const float*)d_in[25];
    const float* fc1_b = (const float*)d_in[26];
    const float* fc2_w = (const float*)d_in[27];
    const float* fc2_b = (const float*)d_in[28];
    float* out = (float*)d_out;

    float *s1n, *s2p, *s3;
    cudaGetSymbolAddress((void**)&s1n, g_s1n);
    cudaGetSymbolAddress((void**)&s2p, g_s2p);
    cudaGetSymbolAddress((void**)&s3,  g_s3);

    // dynamic smem: A double (2*18432B) + B double (2*8192B) = 53248B
    const int dynsz = 2 * 128 * 36 * 4 + 2 * 2048 * 4;
    cudaFuncSetAttribute(gemm2_kernel, cudaFuncAttributeMaxDynamicSharedMemorySize, dynsz);

    coef_kernel<<<1, 224>>>(c1_k, c1_sw, c2_k, c2_sw, c3_k, c3_sw);
    rearrange_wB<<<(27 * 4 * 8 * 32 * 2 + 255) / 256, 256>>>(c2_w);
    pad_x_kernel<<<(2 * 262144 + 255) / 256, 256>>>(x);

    block1_kernel<<<dim3(32768 / 128, 2, 2), 128>>>(
        c1_w, c1_b, c1_w1, c1_w2, bn1_g, bn1_b, s1n);

    gemm2_kernel<<<dim3(16, 16, 2), 128, dynsz>>>(
        c2_b, c2_w1, c2_w2, bn2_g, bn2_b, s2p);

    conv_block<64, 8, 20, 128, 2><<<dim3(4, 64, 2), 128>>>(
        s2p, c3_w, c3_b, c3_w1, c3_w2, bn3_g, bn3_b, s3, 96);

    mean_kernel<<<256, 64>>>(s3);
    fc_kernel<<<1, 256>>>(fc1_w, fc1_b, fc2_w, fc2_b, out);
}